// round 2
// baseline (speedup 1.0000x reference)
#include <cuda_runtime.h>

#define T_DIM 4096
#define B_DIM 32
#define D_DIM 64
#define M_DIM 512
#define BT    (B_DIM * T_DIM)      /* 131072 rows */
#define TR    32                   /* rows per tile */
#define NTILES (BT / TR)           /* 4096 */
#define NTH   512

// deterministic global partials (no atomics, fixed-order reductions)
__device__ float g_part_probs[NTILES * M_DIM];   // 8 MB: per-tile sum of samples per m
__device__ float g_part_kl[NTILES];              // per-tile KL sums
__device__ float g_mid[64 * M_DIM];              // stage-2 partials

// Accurate natural log (rel err ~1e-7 incl. x near 1, fast-math-proof).
// ln x = e*ln2 + 2t*(1 + t^2/3 + t^4/5 + t^6/7), t=(m-1)/(m+1), m in [sqrt2/2, sqrt2)
__device__ __forceinline__ float acc_logf(float v) {
    int i = __float_as_int(v);
    int e = ((i >> 23) & 0xFF) - 127;
    float m = __int_as_float((i & 0x007FFFFF) | 0x3F800000);   // [1,2)
    if (m > 1.4142135f) { m *= 0.5f; e += 1; }
    float t = __fdividef(m - 1.0f, m + 1.0f);
    float t2 = t * t;
    float p = fmaf(0.14285715f, t2, 0.2f);
    p = fmaf(p, t2, 0.33333334f);
    p = fmaf(p, t2, 1.0f);
    return fmaf((float)e, 0.69314718f, 2.0f * t * p);
}

__global__ void __launch_bounds__(NTH, 1) vq_main(
    const float* __restrict__ x,    // (B, 64, T)
    const float* __restrict__ u,    // (B, T, M)
    const float* __restrict__ w,    // (M, 64)
    float* __restrict__ out)        // quantized (B*T, 64) [+ scalars appended by finalize]
{
    extern __shared__ float sm[];
    float* ws    = sm;                    // 512*64          = 32768 floats
    float* xs    = ws + M_DIM * D_DIM;    // 32*68 (padded)  =  2176
    float* Ls    = xs + TR * 68;          // 32*512          = 16384 (logits -> numerators)
    float* invs  = Ls + TR * M_DIM;       // 32
    float* klrow = invs + TR;             // 32
    // total 51392 floats = 205568 B

    const int tid  = threadIdx.x;
    const int lane = tid & 31;
    const int wid  = tid >> 5;
    const int tile = blockIdx.x;
    const int row0 = tile * TR;
    const int b    = row0 >> 12;             // row0 / 4096
    const int t0   = row0 & (T_DIM - 1);

    // ---- weight: registers (thread owns m = tid) + smem copy; wsq in regs ----
    const float4* w4 = (const float4*)w;
    float4 wv[16];
#pragma unroll
    for (int j = 0; j < 16; j++) wv[j] = w4[tid * 16 + j];
    float wsq = 0.0f;
#pragma unroll
    for (int j = 0; j < 16; j++) {
        wsq = fmaf(wv[j].x, wv[j].x, wsq);
        wsq = fmaf(wv[j].y, wv[j].y, wsq);
        wsq = fmaf(wv[j].z, wv[j].z, wsq);
        wsq = fmaf(wv[j].w, wv[j].w, wsq);
    }
    {
        float4* ws4 = (float4*)ws;
#pragma unroll
        for (int q = tid; q < M_DIM * (D_DIM / 4); q += NTH) ws4[q] = w4[q];
    }
    // ---- x tile transposed: xs[i][c] = x[b][c][t0+i], coalesced over i ----
#pragma unroll
    for (int q = tid; q < TR * D_DIM; q += NTH) {
        int i = q & 31, c = q >> 5;
        xs[i * 68 + c] = x[(b * D_DIM + c) * T_DIM + t0 + i];
    }
    __syncthreads();

    // ---- GEMM1: l[r][m=tid] = 2*dot(x_r, w_m) - ||w_m||^2 ----
#pragma unroll 1
    for (int r0 = 0; r0 < TR; r0 += 4) {
        float a0 = 0.f, a1 = 0.f, a2 = 0.f, a3 = 0.f;
#pragma unroll
        for (int j = 0; j < 16; j++) {
            float4 wj = wv[j];
            float4 x0 = *(const float4*)&xs[(r0 + 0) * 68 + j * 4];
            float4 x1 = *(const float4*)&xs[(r0 + 1) * 68 + j * 4];
            float4 x2 = *(const float4*)&xs[(r0 + 2) * 68 + j * 4];
            float4 x3 = *(const float4*)&xs[(r0 + 3) * 68 + j * 4];
            a0 = fmaf(x0.x, wj.x, a0); a0 = fmaf(x0.y, wj.y, a0);
            a0 = fmaf(x0.z, wj.z, a0); a0 = fmaf(x0.w, wj.w, a0);
            a1 = fmaf(x1.x, wj.x, a1); a1 = fmaf(x1.y, wj.y, a1);
            a1 = fmaf(x1.z, wj.z, a1); a1 = fmaf(x1.w, wj.w, a1);
            a2 = fmaf(x2.x, wj.x, a2); a2 = fmaf(x2.y, wj.y, a2);
            a2 = fmaf(x2.z, wj.z, a2); a2 = fmaf(x2.w, wj.w, a2);
            a3 = fmaf(x3.x, wj.x, a3); a3 = fmaf(x3.y, wj.y, a3);
            a3 = fmaf(x3.z, wj.z, a3); a3 = fmaf(x3.w, wj.w, a3);
        }
        Ls[(r0 + 0) * M_DIM + tid] = fmaf(2.0f, a0, -wsq);
        Ls[(r0 + 1) * M_DIM + tid] = fmaf(2.0f, a1, -wsq);
        Ls[(r0 + 2) * M_DIM + tid] = fmaf(2.0f, a2, -wsq);
        Ls[(r0 + 3) * M_DIM + tid] = fmaf(2.0f, a3, -wsq);
    }
    __syncthreads();

    // ---- Phase D: per-row softmax stats + sample numerators (warp -> 2 rows) ----
    {
        int rA = wid * 2;
#pragma unroll
        for (int rr = 0; rr < 2; rr++) {
            int r = rA + rr;
            const float* urow = u + (size_t)(row0 + r) * M_DIM;
            float s_el = 0.f, s_ell = 0.f, s_num = 0.f;
#pragma unroll
            for (int j = 0; j < 16; j++) {
                int m = j * 32 + lane;
                float l  = Ls[r * M_DIM + m];
                float el = __expf(l);                   // exp(logit), |l| < ~0.5
                float uu = fmaxf(urow[m], 1e-9f);       // upper clip is a no-op in fp32
                float lu = acc_logf(uu);                // accurate ln(u) < 0
                float q  = __fdividef(el, lu);
                float num = q * q;                      // exp(2l) / ln(u)^2
                s_el += el;
                s_ell = fmaf(el, l, s_ell);
                s_num += num;
                Ls[r * M_DIM + m] = num;                // overwrite logits with numerators
            }
#pragma unroll
            for (int o = 16; o > 0; o >>= 1) {
                s_el  += __shfl_xor_sync(0xffffffffu, s_el,  o);
                s_ell += __shfl_xor_sync(0xffffffffu, s_ell, o);
                s_num += __shfl_xor_sync(0xffffffffu, s_num, o);
            }
            if (lane == 0) {
                invs[r]  = __frcp_rn(s_num);
                klrow[r] = __fdividef(s_ell, s_el)
                         - acc_logf(s_el * (1.0f / 512.0f));  // = sum p*logp + ln M
            }
        }
    }
    __syncthreads();

    // ---- avg-probs partial: thread m=tid sums normalized samples over 32 rows ----
    {
        float s = 0.f;
#pragma unroll
        for (int r = 0; r < TR; r++)
            s = fmaf(Ls[r * M_DIM + tid], invs[r], s);
        g_part_probs[tile * M_DIM + tid] = s;
    }
    // ---- tile KL ----
    if (wid == 0) {
        float k = klrow[lane];
#pragma unroll
        for (int o = 16; o > 0; o >>= 1) k += __shfl_xor_sync(0xffffffffu, k, o);
        if (lane == 0) g_part_kl[tile] = k;
    }

    // ---- GEMM2: quantized[r][d] = inv_r * sum_m numer[r][m] * w[m][d] ----
    {
        int rA = wid * 2, rB = rA + 1;
        float invA = invs[rA], invB = invs[rB];
        float a00 = 0.f, a01 = 0.f, a10 = 0.f, a11 = 0.f;
#pragma unroll 2
        for (int m4 = 0; m4 < M_DIM; m4 += 4) {
            float nA[4], nB[4];
            *(float4*)nA = *(const float4*)&Ls[rA * M_DIM + m4];
            *(float4*)nB = *(const float4*)&Ls[rB * M_DIM + m4];
#pragma unroll
            for (int k = 0; k < 4; k++) {
                float wA = ws[(m4 + k) * D_DIM + lane];
                float wB = ws[(m4 + k) * D_DIM + lane + 32];
                a00 = fmaf(nA[k], wA, a00);
                a01 = fmaf(nA[k], wB, a01);
                a10 = fmaf(nB[k], wA, a10);
                a11 = fmaf(nB[k], wB, a11);
            }
        }
        size_t o0 = (size_t)(row0 + rA) * D_DIM;
        out[o0 + lane]           = a00 * invA;
        out[o0 + lane + 32]      = a01 * invA;
        out[o0 + 64 + lane]      = a10 * invB;
        out[o0 + 64 + lane + 32] = a11 * invB;
    }
}

// stage 2a: reduce 4096 tile partials -> 64 partials per m
__global__ void vq_reduce_a() {
    int c = blockIdx.x;           // 0..63, each handles 64 tiles
    int tid = threadIdx.x;        // 256
#pragma unroll
    for (int h = 0; h < 2; h++) {
        int m = tid + h * 256;
        const float* p = g_part_probs + (size_t)c * 64 * M_DIM + m;
        float s = 0.f;
#pragma unroll 8
        for (int i = 0; i < 64; i++) s += p[i * M_DIM];
        g_mid[c * M_DIM + m] = s;
    }
}

// stage 2b: final KL + perplexity
__global__ void vq_finalize(float* __restrict__ out, int n_quant) {
    int tid = threadIdx.x;        // 512 (= M)
    float s = 0.f;
#pragma unroll 8
    for (int i = 0; i < 64; i++) s += g_mid[i * M_DIM + tid];
    float avg = s * (1.0f / (float)BT);
    float h = avg * acc_logf(avg + 1e-10f);
    float kls = 0.f;
#pragma unroll
    for (int i = 0; i < 8; i++) kls += g_part_kl[tid + i * 512];

    __shared__ float r1[512], r2[512];
    r1[tid] = h; r2[tid] = kls;
    __syncthreads();
    for (int o = 256; o > 0; o >>= 1) {
        if (tid < o) { r1[tid] += r1[tid + o]; r2[tid] += r2[tid + o]; }
        __syncthreads();
    }
    if (tid == 0) {
        out[n_quant]     = r2[0] * (1.0f / (float)B_DIM);  // KL (mean over batch)
        out[n_quant + 1] = __expf(-r1[0]);                 // perplexity
    }
}

extern "C" void kernel_launch(void* const* d_in, const int* in_sizes, int n_in,
                              void* d_out, int out_size) {
    const float* x = (const float*)d_in[0];
    const float* u = (const float*)d_in[1];
    const float* w = (const float*)d_in[2];
    float* out = (float*)d_out;

    // 205568 B dynamic smem (> 48 KB default) — idempotent, capture-safe
    cudaFuncSetAttribute(vq_main, cudaFuncAttributeMaxDynamicSharedMemorySize, 205568);

    vq_main<<<NTILES, NTH, 205568>>>(x, u, w, out);
    vq_reduce_a<<<64, 256>>>();
    vq_finalize<<<1, 512>>>(out, out_size - 2);
}